// round 13
// baseline (speedup 1.0000x reference)
#include <cuda_runtime.h>
#include <cuda_bf16.h>

// Depthwise 3x3 conv, pad=1: x (2,16,256,64,64) fp32, W (256,256,3,3) -> diag only.
#define C_CH   256
#define H_SP   64
#define W_SP   64
#define N_IMG  (2 * 16 * C_CH)   // 8192 images of 64x64
#define HALF_H 32

__device__ __forceinline__ float4 f4zero() { return make_float4(0.f, 0.f, 0.f, 0.f); }

// Horizontal halo for one row: l = previous lane's .w, r = next lane's .x,
// zeroed at the 16-lane group boundaries (each group is an independent strip).
__device__ __forceinline__ void halo(const float4& v, int lane16, float& l, float& r)
{
    l = __shfl_up_sync(0xffffffffu, v.w, 1);
    r = __shfl_down_sync(0xffffffffu, v.x, 1);
    if (lane16 == 0)  l = 0.f;
    if (lane16 == 15) r = 0.f;
}

// 128-thread CTAs: natural regs (~52) -> 9 CTAs/SM -> 36 resident warps
// with the exact same per-warp instruction schedule as the round-9 champion.
__global__ __launch_bounds__(128)
void dwconv3x3_b128_kernel(const float* __restrict__ x,
                           const float* __restrict__ Wf,
                           float* __restrict__ y)
{
    const int tid    = threadIdx.x;
    const int warp   = tid >> 5;
    const int lane   = tid & 31;
    const int lane16 = lane & 15;

    // One warp = one image. Lanes 0-15: rows [0,32). Lanes 16-31: rows [32,64).
    const int image = blockIdx.x * 4 + warp;            // 0..8191
    const int c     = image & (C_CH - 1);
    const int top   = (lane >> 4) * HALF_H;             // 0 or 32
    const int col   = lane16 << 2;                      // 0,4,...,60

    // Diagonal filter W[c][c][ky][kx] — warp-uniform.
    const float* wp = Wf + (size_t)c * (C_CH + 1) * 9;
    const float w00 = __ldg(wp + 0), w01 = __ldg(wp + 1), w02 = __ldg(wp + 2);
    const float w10 = __ldg(wp + 3), w11 = __ldg(wp + 4), w12 = __ldg(wp + 5);
    const float w20 = __ldg(wp + 6), w21 = __ldg(wp + 7), w22 = __ldg(wp + 8);

    const float* xin  = x + (size_t)image * (H_SP * W_SP) + col;
    float*       yout = y + (size_t)image * (H_SP * W_SP) + col;

    // Register sliding window: rows (m)inus, (c)enter, (n)ext + their halos.
    float4 vm, vc, vn;
    float  lm, rm, lc, rc_, ln, rn;

    vm = (top - 1 >= 0) ? __ldg((const float4*)(xin + (top - 1) * W_SP)) : f4zero();
    vc = __ldg((const float4*)(xin + top * W_SP));
    vn = __ldg((const float4*)(xin + (top + 1) * W_SP));
    halo(vm, lane16, lm, rm);
    halo(vc, lane16, lc, rc_);
    halo(vn, lane16, ln, rn);

    // Fully unrolled: all 32 prefetch LDGs visible and UNCONDITIONAL
    // (clamped address, zero-select after) so ptxas can front-batch freely.
    #pragma unroll
    for (int r = 0; r < HALF_H; r++) {
        const int  gpre  = top + r + 2;
        const int  gclmp = (gpre < H_SP - 1) ? gpre : (H_SP - 1);   // always in-bounds
        const bool oob   = (gpre >= H_SP);

        float4 vp = __ldg((const float4*)(xin + gclmp * W_SP));     // unconditional issue
        if (oob) vp = f4zero();                                     // post-load select

        float lp, rp;
        halo(vp, lane16, lp, rp);

        // Compute output row top+r from resident window.
        float4 o;
        o.x = w00*lm   + w01*vm.x + w02*vm.y
            + w10*lc   + w11*vc.x + w12*vc.y
            + w20*ln   + w21*vn.x + w22*vn.y;
        o.y = w00*vm.x + w01*vm.y + w02*vm.z
            + w10*vc.x + w11*vc.y + w12*vc.z
            + w20*vn.x + w21*vn.y + w22*vn.z;
        o.z = w00*vm.y + w01*vm.z + w02*vm.w
            + w10*vc.y + w11*vc.z + w12*vc.w
            + w20*vn.y + w21*vn.z + w22*vn.w;
        o.w = w00*vm.z + w01*vm.w + w02*rm
            + w10*vc.z + w11*vc.w + w12*rc_
            + w20*vn.z + w21*vn.w + w22*rn;

        *(float4*)(yout + (top + r) * W_SP) = o;

        // Slide the window.
        vm = vc; lm = lc; rm = rc_;
        vc = vn; lc = ln; rc_ = rn;
        vn = vp; ln = lp; rn = rp;
    }
}

extern "C" void kernel_launch(void* const* d_in, const int* in_sizes, int n_in,
                              void* d_out, int out_size)
{
    const float* x  = (const float*)d_in[0];   // (S,B,C,H,W) fp32
    const float* Wf = (const float*)d_in[1];   // (C,C,3,3)  fp32
    float* y = (float*)d_out;

    // 4 warps per 128-thread block, one image per warp.
    dwconv3x3_b128_kernel<<<N_IMG / 4, 128>>>(x, Wf, y);
}

// round 14
// speedup vs baseline: 1.0088x; 1.0088x over previous
#include <cuda_runtime.h>
#include <cuda_bf16.h>

// Depthwise 3x3 conv, pad=1: x (2,16,256,64,64) fp32, W (256,256,3,3) -> diag only.
// At the mixed read/write HBM roofline (~5.85 TB/s measured across all schedules).
#define C_CH   256
#define H_SP   64
#define W_SP   64
#define N_IMG  (2 * 16 * C_CH)   // 8192 images of 64x64
#define HALF_H 32

__device__ __forceinline__ float4 f4zero() { return make_float4(0.f, 0.f, 0.f, 0.f); }

// Horizontal halo for one row: l = previous lane's .w, r = next lane's .x,
// zeroed at the 16-lane group boundaries (each group is an independent strip).
__device__ __forceinline__ void halo(const float4& v, int lane16, float& l, float& r)
{
    l = __shfl_up_sync(0xffffffffu, v.w, 1);
    r = __shfl_down_sync(0xffffffffu, v.x, 1);
    if (lane16 == 0)  l = 0.f;
    if (lane16 == 15) r = 0.f;
}

__device__ __forceinline__ float4 conv_row(const float4& vm, float lm, float rm,
                                           const float4& vc, float lc, float rc_,
                                           const float4& vn, float ln, float rn,
                                           float w00, float w01, float w02,
                                           float w10, float w11, float w12,
                                           float w20, float w21, float w22)
{
    float4 o;
    o.x = w00*lm   + w01*vm.x + w02*vm.y
        + w10*lc   + w11*vc.x + w12*vc.y
        + w20*ln   + w21*vn.x + w22*vn.y;
    o.y = w00*vm.x + w01*vm.y + w02*vm.z
        + w10*vc.x + w11*vc.y + w12*vc.z
        + w20*vn.x + w21*vn.y + w22*vn.z;
    o.z = w00*vm.y + w01*vm.z + w02*vm.w
        + w10*vc.y + w11*vc.z + w12*vc.w
        + w20*vn.y + w21*vn.z + w22*vn.w;
    o.w = w00*vm.z + w01*vm.w + w02*rm
        + w10*vc.z + w11*vc.w + w12*rc_
        + w20*vn.z + w21*vn.w + w22*rn;
    return o;
}

__global__ __launch_bounds__(256)
void dwconv3x3_final_kernel(const float* __restrict__ x,
                            const float* __restrict__ Wf,
                            float* __restrict__ y)
{
    const int tid    = threadIdx.x;
    const int warp   = tid >> 5;
    const int lane   = tid & 31;
    const int lane16 = lane & 15;

    // One warp = one image. Lanes 0-15: rows [0,32). Lanes 16-31: rows [32,64).
    const int image = blockIdx.x * 8 + warp;            // 0..8191
    const int c     = image & (C_CH - 1);
    const int top   = (lane >> 4) * HALF_H;             // 0 or 32
    const int col   = lane16 << 2;                      // 0,4,...,60

    // Diagonal filter W[c][c][ky][kx] — warp-uniform.
    const float* wp = Wf + (size_t)c * (C_CH + 1) * 9;
    const float w00 = __ldg(wp + 0), w01 = __ldg(wp + 1), w02 = __ldg(wp + 2);
    const float w10 = __ldg(wp + 3), w11 = __ldg(wp + 4), w12 = __ldg(wp + 5);
    const float w20 = __ldg(wp + 6), w21 = __ldg(wp + 7), w22 = __ldg(wp + 8);

    const float* xin  = x + (size_t)image * (H_SP * W_SP) + col;
    float*       yout = y + (size_t)image * (H_SP * W_SP) + col;

    // Register sliding window: rows (m)inus, (c)enter, (n)ext + their halos.
    float4 vm, vc, vn;
    float  lm, rm, lc, rc_, ln, rn;

    vm = (top - 1 >= 0) ? __ldg((const float4*)(xin + (top - 1) * W_SP)) : f4zero();
    vc = __ldg((const float4*)(xin + top * W_SP));
    vn = __ldg((const float4*)(xin + (top + 1) * W_SP));
    halo(vm, lane16, lm, rm);
    halo(vc, lane16, lc, rc_);
    halo(vn, lane16, ln, rn);

    // Fully unrolled; all prefetch LDGs unconditional (clamped addr + zero-select).
    // Last iteration peeled: its prefetch is dead (window never used again).
    #pragma unroll
    for (int r = 0; r < HALF_H - 1; r++) {
        const int  gpre  = top + r + 2;
        const int  gclmp = (gpre < H_SP - 1) ? gpre : (H_SP - 1);   // always in-bounds
        const bool oob   = (gpre >= H_SP);

        float4 vp = __ldg((const float4*)(xin + gclmp * W_SP));     // unconditional issue
        if (oob) vp = f4zero();                                     // post-load select

        float lp, rp;
        halo(vp, lane16, lp, rp);

        float4 o = conv_row(vm, lm, rm, vc, lc, rc_, vn, ln, rn,
                            w00, w01, w02, w10, w11, w12, w20, w21, w22);
        *(float4*)(yout + (top + r) * W_SP) = o;

        // Slide the window.
        vm = vc; lm = lc; rm = rc_;
        vc = vn; lc = ln; rc_ = rn;
        vn = vp; ln = lp; rn = rp;
    }

    // Peeled final row (r = HALF_H-1): no prefetch needed.
    {
        float4 o = conv_row(vm, lm, rm, vc, lc, rc_, vn, ln, rn,
                            w00, w01, w02, w10, w11, w12, w20, w21, w22);
        *(float4*)(yout + (top + HALF_H - 1) * W_SP) = o;
    }
}

extern "C" void kernel_launch(void* const* d_in, const int* in_sizes, int n_in,
                              void* d_out, int out_size)
{
    const float* x  = (const float*)d_in[0];   // (S,B,C,H,W) fp32
    const float* Wf = (const float*)d_in[1];   // (C,C,3,3)  fp32
    float* y = (float*)d_out;

    dwconv3x3_final_kernel<<<N_IMG / 8, 256>>>(x, Wf, y);
}